// round 1
// baseline (speedup 1.0000x reference)
#include <cuda_runtime.h>
#include <math.h>

#define Dv 1024
#define Hv 2048
#define Ev 8
#define Tmax 8192

// ---- scratch (static device globals: no allocations allowed) ----
__device__ int   g_cnt[Ev];
__device__ int   g_off[Ev + 1];
__device__ int   g_tok[Ev * Tmax];
__device__ float g_wt [Ev * Tmax];
__device__ float g_hbuf[(size_t)2 * Tmax * Hv];   // 16384 x 2048 fp32 = 128 MB

// ---------------- init ----------------
__global__ void init_kernel() {
    if (threadIdx.x < Ev) g_cnt[threadIdx.x] = 0;
}

// ---------------- router: logits + top2 + softmax + bucket scatter ----------------
__global__ void router_kernel(const float* __restrict__ x, const float* __restrict__ rw) {
    int gt   = blockIdx.x * blockDim.x + threadIdx.x;
    int t    = gt >> 5;
    int lane = gt & 31;
    if (t >= Tmax) return;

    const float* xr = x + (size_t)t * Dv;
    float acc[Ev];
#pragma unroll
    for (int e = 0; e < Ev; e++) acc[e] = 0.0f;

    for (int i = lane; i < Dv; i += 32) {
        float xv = xr[i];
        const float* r = rw + i * Ev;
#pragma unroll
        for (int e = 0; e < Ev; e++) acc[e] += xv * r[e];
    }
#pragma unroll
    for (int o = 16; o; o >>= 1) {
#pragma unroll
        for (int e = 0; e < Ev; e++) acc[e] += __shfl_xor_sync(0xffffffffu, acc[e], o);
    }
    if (lane == 0) {
        // top-1 (strict >, so ties pick the lower index, matching jax top_k)
        int i0 = 0; float v0 = acc[0];
#pragma unroll
        for (int e = 1; e < Ev; e++) if (acc[e] > v0) { v0 = acc[e]; i0 = e; }
        int i1 = -1; float v1 = -3.0e38f;
#pragma unroll
        for (int e = 0; e < Ev; e++) if (e != i0 && acc[e] > v1) { v1 = acc[e]; i1 = e; }
        // softmax over [v0, v1]
        float e1  = expf(v1 - v0);
        float inv = 1.0f / (1.0f + e1);
        float w0  = inv;
        float w1  = e1 * inv;
        int s0 = atomicAdd(&g_cnt[i0], 1);
        g_tok[i0 * Tmax + s0] = t; g_wt[i0 * Tmax + s0] = w0;
        int s1 = atomicAdd(&g_cnt[i1], 1);
        g_tok[i1 * Tmax + s1] = t; g_wt[i1 * Tmax + s1] = w1;
    }
}

// ---------------- exclusive prefix offsets ----------------
__global__ void offsets_kernel() {
    if (threadIdx.x == 0) {
        int o = 0;
#pragma unroll
        for (int e = 0; e < Ev; e++) { g_off[e] = o; o += g_cnt[e]; }
        g_off[Ev] = o;
    }
}

__device__ __forceinline__ float silu_f(float g) {
    return g * (1.0f / (1.0f + __expf(-g)));
}

// ---------------- GEMM1: per-expert gathered  H = (X@W1) * silu(X@Wg) ----------------
// Block tile 128(M) x 64(N), K-step 16, 256 threads, 8x4 microtile, dual accumulators.
__global__ __launch_bounds__(256) void gemm1_kernel(
    const float* __restrict__ x,
    const float* __restrict__ w1,
    const float* __restrict__ wg)
{
    int e   = blockIdx.z;
    int cnt = g_cnt[e];
    int m0  = blockIdx.y * 128;
    if (m0 >= cnt) return;
    int n0  = blockIdx.x * 64;

    const float* W1 = w1 + (size_t)e * Dv * Hv + n0;
    const float* WG = wg + (size_t)e * Dv * Hv + n0;

    __shared__ float As [16][128];
    __shared__ float B1s[16][64];
    __shared__ float BGs[16][64];

    int tid = threadIdx.x;
    int tx  = tid & 15;      // N micro-col group (4 cols)
    int ty  = tid >> 4;      // M micro-row group (8 rows)

    // A loads: 128x16 floats = 512 float4; 2 per thread
    int am0 = tid >> 2;            // 0..63
    int ak0 = (tid & 3) * 4;       // 0,4,8,12
    int am1 = am0 + 64;
    const int* tokp = g_tok + e * Tmax + m0;
    int tokA0 = (m0 + am0 < cnt) ? tokp[am0] : -1;
    int tokA1 = (m0 + am1 < cnt) ? tokp[am1] : -1;
    const float* xA0 = x + (size_t)(tokA0 < 0 ? 0 : tokA0) * Dv + ak0;
    const float* xA1 = x + (size_t)(tokA1 < 0 ? 0 : tokA1) * Dv + ak0;

    // B loads: 16x64 floats = 256 float4; 1 per thread (per matrix)
    int bk = tid >> 4;          // 0..15
    int bn = (tid & 15) * 4;    // 0..60

    float accU[8][4], accG[8][4];
#pragma unroll
    for (int i = 0; i < 8; i++)
#pragma unroll
        for (int j = 0; j < 4; j++) { accU[i][j] = 0.0f; accG[i][j] = 0.0f; }

    for (int kt = 0; kt < Dv / 16; kt++) {
        int kb = kt * 16;
        float4 a0 = (tokA0 >= 0) ? *(const float4*)(xA0 + kb) : make_float4(0, 0, 0, 0);
        float4 a1 = (tokA1 >= 0) ? *(const float4*)(xA1 + kb) : make_float4(0, 0, 0, 0);
        float4 b1 = *(const float4*)(W1 + (size_t)(kb + bk) * Hv + bn);
        float4 bg = *(const float4*)(WG + (size_t)(kb + bk) * Hv + bn);

        As[ak0 + 0][am0] = a0.x; As[ak0 + 1][am0] = a0.y;
        As[ak0 + 2][am0] = a0.z; As[ak0 + 3][am0] = a0.w;
        As[ak0 + 0][am1] = a1.x; As[ak0 + 1][am1] = a1.y;
        As[ak0 + 2][am1] = a1.z; As[ak0 + 3][am1] = a1.w;
        *(float4*)&B1s[bk][bn] = b1;
        *(float4*)&BGs[bk][bn] = bg;
        __syncthreads();

#pragma unroll
        for (int k = 0; k < 16; k++) {
            float a[8];
            *(float4*)&a[0] = *(const float4*)&As[k][ty * 8];
            *(float4*)&a[4] = *(const float4*)&As[k][ty * 8 + 4];
            float4 b1v = *(const float4*)&B1s[k][tx * 4];
            float4 bgv = *(const float4*)&BGs[k][tx * 4];
            float bu[4] = { b1v.x, b1v.y, b1v.z, b1v.w };
            float bg4[4] = { bgv.x, bgv.y, bgv.z, bgv.w };
#pragma unroll
            for (int i = 0; i < 8; i++) {
#pragma unroll
                for (int j = 0; j < 4; j++) {
                    accU[i][j] += a[i] * bu[j];
                    accG[i][j] += a[i] * bg4[j];
                }
            }
        }
        __syncthreads();
    }

    int base = g_off[e];
#pragma unroll
    for (int i = 0; i < 8; i++) {
        int m = m0 + ty * 8 + i;
        if (m < cnt) {
            float4 o;
            o.x = accU[i][0] * silu_f(accG[i][0]);
            o.y = accU[i][1] * silu_f(accG[i][1]);
            o.z = accU[i][2] * silu_f(accG[i][2]);
            o.w = accU[i][3] * silu_f(accG[i][3]);
            *(float4*)(g_hbuf + (size_t)(base + m) * Hv + n0 + tx * 4) = o;
        }
    }
}

// ---------------- GEMM2: Y = H @ W2, scaled scatter-add into out ----------------
// Block tile 128(M) x 128(N), K-step 8, 256 threads, 8x8 microtile.
__global__ __launch_bounds__(256) void gemm2_kernel(
    const float* __restrict__ w2, float* __restrict__ out)
{
    int e   = blockIdx.z;
    int cnt = g_cnt[e];
    int m0  = blockIdx.y * 128;
    if (m0 >= cnt) return;
    int n0  = blockIdx.x * 128;
    int base = g_off[e];

    const float* W2 = w2 + (size_t)e * Hv * Dv + n0;

    __shared__ float As[8][128];
    __shared__ float Bs[8][128];

    int tid = threadIdx.x;
    int tx  = tid & 15;
    int ty  = tid >> 4;

    // A loads: 128x8 = 256 float4; 1 per thread
    int am = tid >> 1;          // 0..127
    int ak = (tid & 1) * 4;     // 0 or 4
    bool avalid = (m0 + am) < cnt;
    const float* aptr = g_hbuf + (size_t)(base + (avalid ? m0 + am : 0)) * Hv + ak;

    // B loads: 8x128 = 256 float4; 1 per thread
    int bk = tid >> 5;          // 0..7
    int bn = (tid & 31) * 4;    // 0..124

    float acc[8][8];
#pragma unroll
    for (int i = 0; i < 8; i++)
#pragma unroll
        for (int j = 0; j < 8; j++) acc[i][j] = 0.0f;

    for (int kt = 0; kt < Hv / 8; kt++) {
        int kb = kt * 8;
        float4 a = avalid ? *(const float4*)(aptr + kb) : make_float4(0, 0, 0, 0);
        float4 b = *(const float4*)(W2 + (size_t)(kb + bk) * Dv + bn);

        As[ak + 0][am] = a.x; As[ak + 1][am] = a.y;
        As[ak + 2][am] = a.z; As[ak + 3][am] = a.w;
        *(float4*)&Bs[bk][bn] = b;
        __syncthreads();

#pragma unroll
        for (int k = 0; k < 8; k++) {
            float av[8], bv[8];
            *(float4*)&av[0] = *(const float4*)&As[k][ty * 8];
            *(float4*)&av[4] = *(const float4*)&As[k][ty * 8 + 4];
            *(float4*)&bv[0] = *(const float4*)&Bs[k][tx * 8];
            *(float4*)&bv[4] = *(const float4*)&Bs[k][tx * 8 + 4];
#pragma unroll
            for (int i = 0; i < 8; i++)
#pragma unroll
                for (int j = 0; j < 8; j++)
                    acc[i][j] += av[i] * bv[j];
        }
        __syncthreads();
    }

#pragma unroll
    for (int i = 0; i < 8; i++) {
        int m = m0 + ty * 8 + i;
        if (m < cnt) {
            int   tok = g_tok[e * Tmax + m];
            float w   = g_wt [e * Tmax + m];
            float* orow = out + (size_t)tok * Dv + n0 + tx * 8;
#pragma unroll
            for (int j = 0; j < 8; j++)
                atomicAdd(orow + j, w * acc[i][j]);
        }
    }
}

// ---------------- launch ----------------
extern "C" void kernel_launch(void* const* d_in, const int* in_sizes, int n_in,
                              void* d_out, int out_size)
{
    const float* x  = (const float*)d_in[0];
    const float* rw = (const float*)d_in[1];
    const float* w1 = (const float*)d_in[2];
    const float* wg = (const float*)d_in[3];
    const float* w2 = (const float*)d_in[4];
    float* out = (float*)d_out;

    cudaMemsetAsync(out, 0, (size_t)out_size * sizeof(float));
    init_kernel<<<1, 32>>>();
    router_kernel<<<(Tmax * 32) / 256, 256>>>(x, rw);
    offsets_kernel<<<1, 1>>>();

    dim3 g1(Hv / 64, Tmax / 128, Ev);     // worst-case m-tiles; blocks early-exit on count
    gemm1_kernel<<<g1, 256>>>(x, w1, wg);

    dim3 g2(Dv / 128, Tmax / 128, Ev);
    gemm2_kernel<<<g2, 256>>>(w2, out);
}